// round 9
// baseline (speedup 1.0000x reference)
#include <cuda_runtime.h>
#include <math.h>

constexpr int Bn=32, Nn=577, Dn=384, Ln=12, Rn=4, Hn=1536, MP=592;
constexpr long XSZ=(long)Bn*Nn*Dn, MSZ=(long)Bn*MP*Dn, SSZ=(long)Bn*Nn*MP, HSZ=(long)Bn*Nn*Hn;

__device__ __align__(16) float g_x[XSZ], g_xn[XSZ], g_q[XSZ], g_ao[XSZ];
__device__ __align__(16) float g_mem[MSZ], g_k[MSZ], g_v[MSZ];
__device__ __align__(16) float g_s[SSZ];
__device__ __align__(16) float g_h[HSZ];
__device__ __align__(16) float g_hist[(long)Rn*Bn*Dn];

__global__ void k_save_cls(const float* __restrict__ x, float* __restrict__ dst){
    int i = blockIdx.x*256 + threadIdx.x;
    if (i >= Bn*Dn) return;
    int b = i/Dn, d = i%Dn;
    dst[i] = x[(long)b*Nn*Dn + d];
}
__global__ void k_restore_body(const float* __restrict__ xin, float* __restrict__ x){
    long i = (long)blockIdx.x*256 + threadIdx.x;
    const long per = (long)(Nn-1)*Dn, tot = (long)Bn*per;
    if (i >= tot) return;
    int b = (int)(i/per); long rem = i - (long)b*per;
    long off = (long)b*Nn*Dn + Dn + rem;
    x[off] = xin[off];
}
__global__ void k_build_mem(const float* __restrict__ x, const float* __restrict__ hist,
                            float* __restrict__ mem, int Mr){
    long i = (long)blockIdx.x*256 + threadIdx.x;
    if (i >= MSZ) return;
    int d = (int)(i % Dn); long bt = i / Dn;
    int t = (int)(bt % MP), b = (int)(bt / MP);
    float v = 0.f;
    if (t < Nn)      v = x[((long)b*Nn + t)*Dn + d];
    else if (t < Mr) v = hist[((long)(t-Nn)*Bn + b)*Dn + d];
    mem[i] = v;
}

// LayerNorm over rows of width 384; 128 threads/row; in-place safe.
__global__ void k_ln(const float* __restrict__ in, float* __restrict__ out,
                     const float* __restrict__ w, const float* __restrict__ bb){
    long row = blockIdx.x;
    const float* x = in + row*Dn; float* y = out + row*Dn;
    int t = threadIdx.x;
    float v0=x[t], v1=x[t+128], v2=x[t+256];
    __shared__ float sm[4];
    float s = v0+v1+v2;
    #pragma unroll
    for (int o=16;o>0;o>>=1) s += __shfl_xor_sync(0xffffffffu,s,o);
    if ((t&31)==0) sm[t>>5]=s;
    __syncthreads();
    float mu = (sm[0]+sm[1]+sm[2]+sm[3])*(1.f/Dn);
    float c0=v0-mu, c1=v1-mu, c2=v2-mu;
    float q = c0*c0+c1*c1+c2*c2;
    #pragma unroll
    for (int o=16;o>0;o>>=1) q += __shfl_xor_sync(0xffffffffu,q,o);
    __syncthreads();
    if ((t&31)==0) sm[t>>5]=q;
    __syncthreads();
    float rs = rsqrtf((sm[0]+sm[1]+sm[2]+sm[3])*(1.f/Dn) + 1e-6f);
    y[t]     = c0*rs*w[t]     + bb[t];
    y[t+128] = c1*rs*w[t+128] + bb[t+128];
    y[t+256] = c2*rs*w[t+256] + bb[t+256];
}

// Softmax over valid width Mr, zero pad cols [Mr, MP). 256 thr/row.
__global__ void k_softmax(float* __restrict__ sbuf, int Mr){
    long row = blockIdx.x;
    float* p = sbuf + row*MP;
    int t = threadIdx.x;
    float v[3]; float mx = -3.0e38f;
    #pragma unroll
    for (int i=0;i<3;++i){ int idx=t+256*i; v[i] = (idx<Mr)? p[idx] : -3.0e38f; mx = fmaxf(mx,v[i]); }
    __shared__ float sm[8];
    #pragma unroll
    for (int o=16;o>0;o>>=1) mx = fmaxf(mx,__shfl_xor_sync(0xffffffffu,mx,o));
    if ((t&31)==0) sm[t>>5]=mx;
    __syncthreads();
    float m2 = sm[0];
    #pragma unroll
    for (int i=1;i<8;++i) m2 = fmaxf(m2,sm[i]);
    float sum = 0.f;
    #pragma unroll
    for (int i=0;i<3;++i){ int idx=t+256*i; if (idx<Mr){ v[i]=expf(v[i]-m2); sum+=v[i]; } }
    #pragma unroll
    for (int o=16;o>0;o>>=1) sum += __shfl_xor_sync(0xffffffffu,sum,o);
    __syncthreads();
    if ((t&31)==0) sm[t>>5]=sum;
    __syncthreads();
    float tot=0.f;
    #pragma unroll
    for (int i=0;i<8;++i) tot += sm[i];
    float inv = 1.f/tot;
    #pragma unroll
    for (int i=0;i<3;++i){ int idx=t+256*i; if (idx<Mr) p[idx]=v[i]*inv; else if (idx<MP) p[idx]=0.f; }
}

// SGEMM 128x128x16, 256 thr, 8x8 microtile. BT: B is [Nc,K] (row=k-contig). K%16==0.
constexpr int BM=128, BN=128, BKT=16;
constexpr int EPI_SCALE=0, EPI_BIAS=1, EPI_LSRES=2, EPI_GELU=3;

template<int EPI, bool BT>
__launch_bounds__(256,2)
__global__ void k_gemm(const float* __restrict__ A, int lda,
                       const float* __restrict__ Bm, int ldb,
                       const float* __restrict__ bias, const float* __restrict__ ls,
                       const float* __restrict__ res, float* __restrict__ C, int ldc,
                       int Mrows, int Ncols, int K,
                       long sA, long sB, long sC, float alpha){
    long zb = blockIdx.z;
    A += zb*sA; Bm += zb*sB; C += zb*sC;
    const float* resp = (EPI==EPI_LSRES) ? (res + zb*sC) : nullptr;

    __shared__ __align__(16) float As[BKT][BM+4];
    __shared__ __align__(16) float Bs[BKT][BN+4];

    int tid = threadIdx.x;
    int bm = blockIdx.y*BM, bn = blockIdx.x*BN;
    int tx = tid & 15, ty = tid >> 4;
    float acc[8][8];
    #pragma unroll
    for (int i=0;i<8;++i)
        #pragma unroll
        for (int j=0;j<8;++j) acc[i][j]=0.f;

    int lrow = tid>>2, lk4 = (tid&3)<<2;
    int nk = K>>4;
    for (int kt=0; kt<nk; ++kt){
        int k0 = kt*BKT;
        #pragma unroll
        for (int p=0;p<2;++p){
            int r = lrow + p*64, gm = bm + r;
            float4 v = make_float4(0.f,0.f,0.f,0.f);
            if (gm < Mrows) v = *(const float4*)(A + (long)gm*lda + k0 + lk4);
            As[lk4+0][r]=v.x; As[lk4+1][r]=v.y; As[lk4+2][r]=v.z; As[lk4+3][r]=v.w;
        }
        if (BT){
            #pragma unroll
            for (int p=0;p<2;++p){
                int r = lrow + p*64, gn = bn + r;
                float4 v = make_float4(0.f,0.f,0.f,0.f);
                if (gn < Ncols) v = *(const float4*)(Bm + (long)gn*ldb + k0 + lk4);
                Bs[lk4+0][r]=v.x; Bs[lk4+1][r]=v.y; Bs[lk4+2][r]=v.z; Bs[lk4+3][r]=v.w;
            }
        } else {
            int brow = tid>>5, bc4 = (tid&31)<<2;
            #pragma unroll
            for (int p=0;p<2;++p){
                int kk = brow + p*8, gn = bn + bc4;
                float4 v = make_float4(0.f,0.f,0.f,0.f);
                if (gn < Ncols) v = *(const float4*)(Bm + (long)(k0+kk)*ldb + gn);
                *(float4*)&Bs[kk][bc4] = v;
            }
        }
        __syncthreads();
        #pragma unroll
        for (int kk=0; kk<BKT; ++kk){
            float4 a0 = *(const float4*)&As[kk][ty*4];
            float4 a1 = *(const float4*)&As[kk][64+ty*4];
            float4 b0 = *(const float4*)&Bs[kk][tx*4];
            float4 b1 = *(const float4*)&Bs[kk][64+tx*4];
            float a[8]={a0.x,a0.y,a0.z,a0.w,a1.x,a1.y,a1.z,a1.w};
            float b[8]={b0.x,b0.y,b0.z,b0.w,b1.x,b1.y,b1.z,b1.w};
            #pragma unroll
            for (int i=0;i<8;++i)
                #pragma unroll
                for (int j=0;j<8;++j) acc[i][j]=fmaf(a[i],b[j],acc[i][j]);
        }
        __syncthreads();
    }
    #pragma unroll
    for (int i=0;i<8;++i){
        int gm = bm + ((i<4)? (ty*4+i) : (64+ty*4+(i-4)));
        if (gm >= Mrows) continue;
        long ro = (long)gm*ldc;
        #pragma unroll
        for (int j=0;j<8;++j){
            int gn = bn + ((j<4)? (tx*4+j) : (64+tx*4+(j-4)));
            if (gn >= Ncols) continue;
            float v = acc[i][j];
            if      (EPI==EPI_SCALE) v *= alpha;
            else if (EPI==EPI_BIAS)  v += bias[gn];
            else if (EPI==EPI_LSRES) v = (v + bias[gn])*ls[gn] + resp[ro+gn];
            else { v += bias[gn]; v = 0.5f*v*(1.f + erff(v*0.70710678118654752f)); }
            C[ro+gn] = v;
        }
    }
}

static inline unsigned cdiv(long a, long b){ return (unsigned)((a+b-1)/b); }

static void gemm(int epi, bool bt, const float* A, int lda, const float* B, int ldb,
                 const float* bias, const float* ls, const float* res, float* C, int ldc,
                 int M, int Nc, int K, int zb, long sA, long sB, long sC, float alpha){
    dim3 g(cdiv(Nc,BN), cdiv(M,BM), zb), t(256);
    #define GL(E,T) k_gemm<E,T><<<g,t>>>(A,lda,B,ldb,bias,ls,res,C,ldc,M,Nc,K,sA,sB,sC,alpha)
    if (bt){
        if      (epi==EPI_SCALE) GL(EPI_SCALE,true);
        else if (epi==EPI_BIAS)  GL(EPI_BIAS,true);
        else if (epi==EPI_LSRES) GL(EPI_LSRES,true);
        else                     GL(EPI_GELU,true);
    } else {
        if      (epi==EPI_SCALE) GL(EPI_SCALE,false);
        else if (epi==EPI_BIAS)  GL(EPI_BIAS,false);
        else if (epi==EPI_LSRES) GL(EPI_LSRES,false);
        else                     GL(EPI_GELU,false);
    }
    #undef GL
}

extern "C" void kernel_launch(void* const* d_in, const int* in_sizes, int n_in,
                              void* d_out, int out_size){
    const float* in_x     = (const float*)d_in[0];
    const float* norm1_w  = (const float*)d_in[1];
    const float* norm1_b  = (const float*)d_in[2];
    const float* qkv_w    = (const float*)d_in[3];
    const float* qkv_b    = (const float*)d_in[4];
    const float* qn_w     = (const float*)d_in[5];
    const float* qn_b     = (const float*)d_in[6];
    const float* kn_w     = (const float*)d_in[7];
    const float* kn_b     = (const float*)d_in[8];
    const float* an_w     = (const float*)d_in[9];
    const float* an_b     = (const float*)d_in[10];
    const float* proj_w   = (const float*)d_in[11];
    const float* proj_b   = (const float*)d_in[12];
    const float* ls1      = (const float*)d_in[13];
    const float* norm2_w  = (const float*)d_in[14];
    const float* norm2_b  = (const float*)d_in[15];
    const float* fc1_w    = (const float*)d_in[16];
    const float* fc1_b    = (const float*)d_in[17];
    const float* fc2_w    = (const float*)d_in[18];
    const float* fc2_b    = (const float*)d_in[19];
    const float* ls2      = (const float*)d_in[20];

    float *px,*pxn,*pq,*pao,*pmem,*pk,*pv,*ps,*ph,*phist;
    cudaGetSymbolAddress((void**)&px,   g_x);
    cudaGetSymbolAddress((void**)&pxn,  g_xn);
    cudaGetSymbolAddress((void**)&pq,   g_q);
    cudaGetSymbolAddress((void**)&pao,  g_ao);
    cudaGetSymbolAddress((void**)&pmem, g_mem);
    cudaGetSymbolAddress((void**)&pk,   g_k);
    cudaGetSymbolAddress((void**)&pv,   g_v);
    cudaGetSymbolAddress((void**)&ps,   g_s);
    cudaGetSymbolAddress((void**)&ph,   g_h);
    cudaGetSymbolAddress((void**)&phist,g_hist);

    const float scale = 1.0f / sqrtf((float)Dn);
    const int MX = Bn*Nn;          // 18464 x-rows
    const int MM = Bn*MP;          // 18944 mem-rows

    cudaMemcpyAsync(px, in_x, XSZ*sizeof(float), cudaMemcpyDeviceToDevice);

    for (int r = 0; r < Rn; ++r){
        int Mr = Nn + r;
        k_save_cls<<<cdiv(Bn*Dn,256),256>>>(px, phist + (long)r*Bn*Dn);
        k_restore_body<<<cdiv((long)Bn*(Nn-1)*Dn,256),256>>>(in_x, px);
        k_build_mem<<<cdiv(MSZ,256),256>>>(px, phist, pmem, Mr);

        for (int l = 0; l < Ln; ++l){
            const float* wq = qkv_w + (long)l*3*Dn*Dn;
            const float* wk = wq + (long)Dn*Dn;
            const float* wv = wk + (long)Dn*Dn;
            const float* bq = qkv_b + (long)l*3*Dn;
            const float* bk = bq + Dn;
            const float* bv = bk + Dn;

            // xn = LN(x); q = LN(xn@Wq^T + bq)
            k_ln<<<MX,128>>>(px, pxn, norm1_w + (long)l*Dn, norm1_b + (long)l*Dn);
            gemm(EPI_BIAS, true, pxn, Dn, wq, Dn, bq, 0, 0, pq, Dn, MX, Dn, Dn, 1,0,0,0, 0.f);
            k_ln<<<MX,128>>>(pq, pq, qn_w + (long)l*Dn, qn_b + (long)l*Dn);
            // k = LN(mem@Wk^T + bk); v = mem@Wv^T + bv
            gemm(EPI_BIAS, true, pmem, Dn, wk, Dn, bk, 0, 0, pk, Dn, MM, Dn, Dn, 1,0,0,0, 0.f);
            k_ln<<<MM,128>>>(pk, pk, kn_w + (long)l*Dn, kn_b + (long)l*Dn);
            gemm(EPI_BIAS, true, pmem, Dn, wv, Dn, bv, 0, 0, pv, Dn, MM, Dn, Dn, 1,0,0,0, 0.f);
            // scores = q@k^T * scale (batched), softmax, ao = s@v
            gemm(EPI_SCALE, true, pq, Dn, pk, Dn, 0,0,0, ps, MP, Nn, MP, Dn,
                 Bn, (long)Nn*Dn, (long)MP*Dn, (long)Nn*MP, scale);
            k_softmax<<<MX,256>>>(ps, Mr);
            gemm(EPI_SCALE, false, ps, MP, pv, Dn, 0,0,0, pao, Dn, Nn, Dn, MP,
                 Bn, (long)Nn*MP, (long)MP*Dn, (long)Nn*Dn, 1.0f);
            // ao = LN(ao); x_new(pxn) = (ao@Wp^T + bp)*ls1 + x
            k_ln<<<MX,128>>>(pao, pao, an_w + (long)l*Dn, an_b + (long)l*Dn);
            gemm(EPI_LSRES, true, pao, Dn, proj_w + (long)l*Dn*Dn, Dn,
                 proj_b + (long)l*Dn, ls1 + (long)l*Dn, px, pxn, Dn, MX, Dn, Dn, 1,0,0,0, 0.f);
            // MLP: q = LN(pxn); h = gelu(q@W1^T+b1); x = (h@W2^T+b2)*ls2 + pxn
            k_ln<<<MX,128>>>(pxn, pq, norm2_w + (long)l*Dn, norm2_b + (long)l*Dn);
            gemm(EPI_GELU, true, pq, Dn, fc1_w + (long)l*Hn*Dn, Dn,
                 fc1_b + (long)l*Hn, 0, 0, ph, Hn, MX, Hn, Dn, 1,0,0,0, 0.f);
            gemm(EPI_LSRES, true, ph, Hn, fc2_w + (long)l*Dn*Hn, Hn,
                 fc2_b + (long)l*Dn, ls2 + (long)l*Dn, pxn, px, Dn, MX, Dn, Hn, 1,0,0,0, 0.f);
        }
    }
    cudaMemcpyAsync(d_out, px, XSZ*sizeof(float), cudaMemcpyDeviceToDevice);
}

// round 10
// speedup vs baseline: 1.3040x; 1.3040x over previous
#include <cuda_runtime.h>
#include <math.h>

constexpr int Bn=32, Nn=577, Dn=384, Ln=12, Rn=4, Hn=1536, MP=592;
constexpr long XSZ=(long)Bn*Nn*Dn, MSZ=(long)Bn*MP*Dn, SSZ=(long)Bn*Nn*MP, HSZ=(long)Bn*Nn*Hn;

__device__ __align__(16) float g_x[XSZ], g_xn[XSZ], g_q[XSZ], g_ao[XSZ];
__device__ __align__(16) float g_mem[MSZ], g_k[MSZ], g_v[MSZ], g_vt[MSZ];
__device__ __align__(16) float g_s[SSZ];
__device__ __align__(16) float g_h[HSZ];
__device__ __align__(16) float g_hist[(long)Rn*Bn*Dn];

__global__ void k_save_cls(const float* __restrict__ x, float* __restrict__ dst){
    int i = blockIdx.x*256 + threadIdx.x;
    if (i >= Bn*Dn) return;
    int b = i/Dn, d = i%Dn;
    dst[i] = x[(long)b*Nn*Dn + d];
}
__global__ void k_restore_body(const float* __restrict__ xin, float* __restrict__ x){
    long i = (long)blockIdx.x*256 + threadIdx.x;
    const long per = (long)(Nn-1)*Dn, tot = (long)Bn*per;
    if (i >= tot) return;
    int b = (int)(i/per); long rem = i - (long)b*per;
    long off = (long)b*Nn*Dn + Dn + rem;
    x[off] = xin[off];
}
__global__ void k_build_mem(const float* __restrict__ x, const float* __restrict__ hist,
                            float* __restrict__ mem, int Mr){
    long i = (long)blockIdx.x*256 + threadIdx.x;
    if (i >= MSZ) return;
    int d = (int)(i % Dn); long bt = i / Dn;
    int t = (int)(bt % MP), b = (int)(bt / MP);
    float v = 0.f;
    if (t < Nn)      v = x[((long)b*Nn + t)*Dn + d];
    else if (t < Mr) v = hist[((long)(t-Nn)*Bn + b)*Dn + d];
    mem[i] = v;
}

// batched transpose: v [B][MP][Dn] -> vt [B][Dn][MP]
__global__ void k_transpose(const float* __restrict__ v, float* __restrict__ vt){
    __shared__ float tile[32][33];
    int b = blockIdx.z;
    int t0 = blockIdx.x*32, d0 = blockIdx.y*32;
    const float* src = v + (long)b*MP*Dn;
    float* dst = vt + (long)b*Dn*MP;
    int x = threadIdx.x, y = threadIdx.y;
    #pragma unroll
    for (int i=0;i<32;i+=8){
        int t=t0+y+i, d=d0+x;
        if (t<MP && d<Dn) tile[y+i][x] = src[(long)t*Dn+d];
    }
    __syncthreads();
    #pragma unroll
    for (int i=0;i<32;i+=8){
        int d=d0+y+i, t=t0+x;
        if (d<Dn && t<MP) dst[(long)d*MP+t] = tile[x][y+i];
    }
}

__global__ void k_ln(const float* __restrict__ in, float* __restrict__ out,
                     const float* __restrict__ w, const float* __restrict__ bb){
    long row = blockIdx.x;
    const float* x = in + row*Dn; float* y = out + row*Dn;
    int t = threadIdx.x;
    float v0=x[t], v1=x[t+128], v2=x[t+256];
    __shared__ float sm[4];
    float s = v0+v1+v2;
    #pragma unroll
    for (int o=16;o>0;o>>=1) s += __shfl_xor_sync(0xffffffffu,s,o);
    if ((t&31)==0) sm[t>>5]=s;
    __syncthreads();
    float mu = (sm[0]+sm[1]+sm[2]+sm[3])*(1.f/Dn);
    float c0=v0-mu, c1=v1-mu, c2=v2-mu;
    float q = c0*c0+c1*c1+c2*c2;
    #pragma unroll
    for (int o=16;o>0;o>>=1) q += __shfl_xor_sync(0xffffffffu,q,o);
    __syncthreads();
    if ((t&31)==0) sm[t>>5]=q;
    __syncthreads();
    float rs = rsqrtf((sm[0]+sm[1]+sm[2]+sm[3])*(1.f/Dn) + 1e-6f);
    y[t]     = c0*rs*w[t]     + bb[t];
    y[t+128] = c1*rs*w[t+128] + bb[t+128];
    y[t+256] = c2*rs*w[t+256] + bb[t+256];
}

__global__ void k_softmax(float* __restrict__ sbuf, int Mr){
    long row = blockIdx.x;
    float* p = sbuf + row*MP;
    int t = threadIdx.x;
    float v[3]; float mx = -3.0e38f;
    #pragma unroll
    for (int i=0;i<3;++i){ int idx=t+256*i; v[i] = (idx<Mr)? p[idx] : -3.0e38f; mx = fmaxf(mx,v[i]); }
    __shared__ float sm[8];
    #pragma unroll
    for (int o=16;o>0;o>>=1) mx = fmaxf(mx,__shfl_xor_sync(0xffffffffu,mx,o));
    if ((t&31)==0) sm[t>>5]=mx;
    __syncthreads();
    float m2 = sm[0];
    #pragma unroll
    for (int i=1;i<8;++i) m2 = fmaxf(m2,sm[i]);
    float sum = 0.f;
    #pragma unroll
    for (int i=0;i<3;++i){ int idx=t+256*i; if (idx<Mr){ v[i]=expf(v[i]-m2); sum+=v[i]; } }
    #pragma unroll
    for (int o=16;o>0;o>>=1) sum += __shfl_xor_sync(0xffffffffu,sum,o);
    __syncthreads();
    if ((t&31)==0) sm[t>>5]=sum;
    __syncthreads();
    float tot=0.f;
    #pragma unroll
    for (int i=0;i<8;++i) tot += sm[i];
    float inv = 1.f/tot;
    #pragma unroll
    for (int i=0;i<3;++i){ int idx=t+256*i; if (idx<Mr) p[idx]=v[i]*inv; else if (idx<MP) p[idx]=0.f; }
}

// ---------------------------------------------------------------------------
// TF32 tensor-core GEMM. C = epi( A[M,K] @ B[Nc,K]^T ). K % 16 == 0.
// 128x128 tile, BK=16, 256 thr = 8 warps (4m x 2n), warp tile 32x64,
// mma.m16n8k8.tf32. smem stride 20 words -> conflict-free fragment loads.
// ---------------------------------------------------------------------------
constexpr int BM=128, BN=128, BK=16, LDSW=20;
constexpr int EPI_SCALE=0, EPI_BIAS=1, EPI_LSRES=2, EPI_GELU=3;

__device__ __forceinline__ unsigned f2tf(float x){
    unsigned u; asm("cvt.rna.tf32.f32 %0, %1;" : "=r"(u) : "f"(x)); return u;
}
__device__ __forceinline__ void mma8(float* c, const unsigned* a, const unsigned* b){
    asm volatile("mma.sync.aligned.m16n8k8.row.col.f32.tf32.tf32.f32 "
        "{%0,%1,%2,%3}, {%4,%5,%6,%7}, {%8,%9}, {%0,%1,%2,%3};"
        : "+f"(c[0]), "+f"(c[1]), "+f"(c[2]), "+f"(c[3])
        : "r"(a[0]), "r"(a[1]), "r"(a[2]), "r"(a[3]), "r"(b[0]), "r"(b[1]));
}

template<int EPI>
__launch_bounds__(256,2)
__global__ void k_gemm_t(const float* __restrict__ A, int lda,
                         const float* __restrict__ Bm, int ldb,
                         const float* __restrict__ bias, const float* __restrict__ ls,
                         const float* __restrict__ res, float* __restrict__ C, int ldc,
                         int Mrows, int Ncols, int K,
                         long sA, long sB, long sC, float alpha){
    long zb = blockIdx.z;
    A += zb*sA; Bm += zb*sB; C += zb*sC;
    const float* resp = (EPI==EPI_LSRES) ? (res + zb*sC) : nullptr;

    __shared__ unsigned As[BM*LDSW];
    __shared__ unsigned Bs[BN*LDSW];

    int tid = threadIdx.x, lane = tid&31, warp = tid>>5;
    int bm = blockIdx.y*BM, bn = blockIdx.x*BN;
    int wm = (warp>>1)*32, wn = (warp&1)*64;
    int gid = lane>>2, tig = lane&3;

    float acc[2][8][4];
    #pragma unroll
    for (int i=0;i<2;++i)
        #pragma unroll
        for (int j=0;j<8;++j)
            #pragma unroll
            for (int q=0;q<4;++q) acc[i][j][q]=0.f;

    int lrow = tid>>2, lk4 = (tid&3)<<2;
    int nk = K>>4;
    for (int kt=0; kt<nk; ++kt){
        int k0 = kt*BK;
        #pragma unroll
        for (int p=0;p<2;++p){
            int r = lrow + p*64;
            int gm = bm + r;
            float4 v = make_float4(0.f,0.f,0.f,0.f);
            if (gm < Mrows) v = *(const float4*)(A + (long)gm*lda + k0 + lk4);
            uint4 u = make_uint4(f2tf(v.x), f2tf(v.y), f2tf(v.z), f2tf(v.w));
            *(uint4*)&As[r*LDSW + lk4] = u;
            int gn = bn + r;
            float4 w = make_float4(0.f,0.f,0.f,0.f);
            if (gn < Ncols) w = *(const float4*)(Bm + (long)gn*ldb + k0 + lk4);
            uint4 uw = make_uint4(f2tf(w.x), f2tf(w.y), f2tf(w.z), f2tf(w.w));
            *(uint4*)&Bs[r*LDSW + lk4] = uw;
        }
        __syncthreads();
        #pragma unroll
        for (int ks=0; ks<2; ++ks){
            int kk = ks*8;
            unsigned af[2][4], bf[8][2];
            #pragma unroll
            for (int mt=0; mt<2; ++mt){
                int m0 = wm + mt*16;
                af[mt][0] = As[(m0+gid  )*LDSW + kk + tig];
                af[mt][1] = As[(m0+gid+8)*LDSW + kk + tig];
                af[mt][2] = As[(m0+gid  )*LDSW + kk + tig + 4];
                af[mt][3] = As[(m0+gid+8)*LDSW + kk + tig + 4];
            }
            #pragma unroll
            for (int nt=0; nt<8; ++nt){
                int n0 = wn + nt*8;
                bf[nt][0] = Bs[(n0+gid)*LDSW + kk + tig];
                bf[nt][1] = Bs[(n0+gid)*LDSW + kk + tig + 4];
            }
            #pragma unroll
            for (int mt=0; mt<2; ++mt)
                #pragma unroll
                for (int nt=0; nt<8; ++nt)
                    mma8(acc[mt][nt], af[mt], bf[nt]);
        }
        __syncthreads();
    }

    #pragma unroll
    for (int mt=0; mt<2; ++mt){
        int row0 = bm + wm + mt*16 + gid;
        #pragma unroll
        for (int nt=0; nt<8; ++nt){
            int col = bn + wn + nt*8 + 2*tig;
            if (col >= Ncols) continue;  // Ncols even -> covers col+1 too
            #pragma unroll
            for (int h=0; h<2; ++h){
                int gm = row0 + h*8;
                if (gm >= Mrows) continue;
                long ro = (long)gm*ldc;
                #pragma unroll
                for (int q=0; q<2; ++q){
                    int gn = col + q;
                    float v = acc[mt][nt][h*2+q];
                    if      (EPI==EPI_SCALE) v *= alpha;
                    else if (EPI==EPI_BIAS)  v += bias[gn];
                    else if (EPI==EPI_LSRES) v = (v + bias[gn])*ls[gn] + resp[ro+gn];
                    else { v += bias[gn]; v = 0.5f*v*(1.f + erff(v*0.70710678118654752f)); }
                    C[ro+gn] = v;
                }
            }
        }
    }
}

static inline unsigned cdiv(long a, long b){ return (unsigned)((a+b-1)/b); }

static void gemm(int epi, const float* A, int lda, const float* B, int ldb,
                 const float* bias, const float* ls, const float* res, float* C, int ldc,
                 int M, int Nc, int K, int zb, long sA, long sB, long sC, float alpha){
    dim3 g(cdiv(Nc,BN), cdiv(M,BM), zb), t(256);
    if      (epi==EPI_SCALE) k_gemm_t<EPI_SCALE><<<g,t>>>(A,lda,B,ldb,bias,ls,res,C,ldc,M,Nc,K,sA,sB,sC,alpha);
    else if (epi==EPI_BIAS)  k_gemm_t<EPI_BIAS ><<<g,t>>>(A,lda,B,ldb,bias,ls,res,C,ldc,M,Nc,K,sA,sB,sC,alpha);
    else if (epi==EPI_LSRES) k_gemm_t<EPI_LSRES><<<g,t>>>(A,lda,B,ldb,bias,ls,res,C,ldc,M,Nc,K,sA,sB,sC,alpha);
    else                     k_gemm_t<EPI_GELU ><<<g,t>>>(A,lda,B,ldb,bias,ls,res,C,ldc,M,Nc,K,sA,sB,sC,alpha);
}

extern "C" void kernel_launch(void* const* d_in, const int* in_sizes, int n_in,
                              void* d_out, int out_size){
    const float* in_x     = (const float*)d_in[0];
    const float* norm1_w  = (const float*)d_in[1];
    const float* norm1_b  = (const float*)d_in[2];
    const float* qkv_w    = (const float*)d_in[3];
    const float* qkv_b    = (const float*)d_in[4];
    const float* qn_w     = (const float*)d_in[5];
    const float* qn_b     = (const float*)d_in[6];
    const float* kn_w     = (const float*)d_in[7];
    const float* kn_b     = (const float*)d_in[8];
    const float* an_w     = (const float*)d_in[9];
    const float* an_b     = (const float*)d_in[10];
    const float* proj_w   = (const float*)d_in[11];
    const float* proj_b   = (const float*)d_in[12];
    const float* ls1      = (const float*)d_in[13];
    const float* norm2_w  = (const float*)d_in[14];
    const float* norm2_b  = (const float*)d_in[15];
    const float* fc1_w    = (const float*)d_in[16];
    const float* fc1_b    = (const float*)d_in[17];
    const float* fc2_w    = (const float*)d_in[18];
    const float* fc2_b    = (const float*)d_in[19];
    const float* ls2      = (const float*)d_in[20];

    float *px,*pxn,*pq,*pao,*pmem,*pk,*pv,*pvt,*ps,*ph,*phist;
    cudaGetSymbolAddress((void**)&px,   g_x);
    cudaGetSymbolAddress((void**)&pxn,  g_xn);
    cudaGetSymbolAddress((void**)&pq,   g_q);
    cudaGetSymbolAddress((void**)&pao,  g_ao);
    cudaGetSymbolAddress((void**)&pmem, g_mem);
    cudaGetSymbolAddress((void**)&pk,   g_k);
    cudaGetSymbolAddress((void**)&pv,   g_v);
    cudaGetSymbolAddress((void**)&pvt,  g_vt);
    cudaGetSymbolAddress((void**)&ps,   g_s);
    cudaGetSymbolAddress((void**)&ph,   g_h);
    cudaGetSymbolAddress((void**)&phist,g_hist);

    const float scale = 1.0f / sqrtf((float)Dn);
    const int MX = Bn*Nn;          // 18464
    const int MM = Bn*MP;          // 18944

    cudaMemcpyAsync(px, in_x, XSZ*sizeof(float), cudaMemcpyDeviceToDevice);

    for (int r = 0; r < Rn; ++r){
        int Mr = Nn + r;
        k_save_cls<<<cdiv(Bn*Dn,256),256>>>(px, phist + (long)r*Bn*Dn);
        k_restore_body<<<cdiv((long)Bn*(Nn-1)*Dn,256),256>>>(in_x, px);
        k_build_mem<<<cdiv(MSZ,256),256>>>(px, phist, pmem, Mr);

        for (int l = 0; l < Ln; ++l){
            const float* wq = qkv_w + (long)l*3*Dn*Dn;
            const float* wk = wq + (long)Dn*Dn;
            const float* wv = wk + (long)Dn*Dn;
            const float* bq = qkv_b + (long)l*3*Dn;
            const float* bk = bq + Dn;
            const float* bv = bk + Dn;

            k_ln<<<MX,128>>>(px, pxn, norm1_w + (long)l*Dn, norm1_b + (long)l*Dn);
            gemm(EPI_BIAS, pxn, Dn, wq, Dn, bq, 0, 0, pq, Dn, MX, Dn, Dn, 1,0,0,0, 0.f);
            k_ln<<<MX,128>>>(pq, pq, qn_w + (long)l*Dn, qn_b + (long)l*Dn);

            gemm(EPI_BIAS, pmem, Dn, wk, Dn, bk, 0, 0, pk, Dn, MM, Dn, Dn, 1,0,0,0, 0.f);
            k_ln<<<MM,128>>>(pk, pk, kn_w + (long)l*Dn, kn_b + (long)l*Dn);
            gemm(EPI_BIAS, pmem, Dn, wv, Dn, bv, 0, 0, pv, Dn, MM, Dn, Dn, 1,0,0,0, 0.f);
            k_transpose<<<dim3(cdiv(MP,32),cdiv(Dn,32),Bn), dim3(32,8)>>>(pv, pvt);

            gemm(EPI_SCALE, pq, Dn, pk, Dn, 0,0,0, ps, MP, Nn, MP, Dn,
                 Bn, (long)Nn*Dn, (long)MP*Dn, (long)Nn*MP, scale);
            k_softmax<<<MX,256>>>(ps, Mr);
            gemm(EPI_SCALE, ps, MP, pvt, MP, 0,0,0, pao, Dn, Nn, Dn, MP,
                 Bn, (long)Nn*MP, (long)Dn*MP, (long)Nn*Dn, 1.0f);

            k_ln<<<MX,128>>>(pao, pao, an_w + (long)l*Dn, an_b + (long)l*Dn);
            gemm(EPI_LSRES, pao, Dn, proj_w + (long)l*Dn*Dn, Dn,
                 proj_b + (long)l*Dn, ls1 + (long)l*Dn, px, pxn, Dn, MX, Dn, Dn, 1,0,0,0, 0.f);

            k_ln<<<MX,128>>>(pxn, pq, norm2_w + (long)l*Dn, norm2_b + (long)l*Dn);
            gemm(EPI_GELU, pq, Dn, fc1_w + (long)l*Hn*Dn, Dn,
                 fc1_b + (long)l*Hn, 0, 0, ph, Hn, MX, Hn, Dn, 1,0,0,0, 0.f);
            gemm(EPI_LSRES, ph, Hn, fc2_w + (long)l*Dn*Hn, Hn,
                 fc2_b + (long)l*Dn, ls2 + (long)l*Dn, pxn, px, Dn, MX, Dn, Hn, 1,0,0,0, 0.f);
        }
    }
    cudaMemcpyAsync(d_out, px, XSZ*sizeof(float), cudaMemcpyDeviceToDevice);
}

// round 13
// speedup vs baseline: 2.1377x; 1.6394x over previous
#include <cuda_runtime.h>
#include <cuda_bf16.h>
#include <math.h>

constexpr int Bn=32, Nn=577, Dn=384, Ln=12, Rn=4, Hn=1536, MP=608;
constexpr long XSZ=(long)Bn*Nn*Dn, MSZ=(long)Bn*MP*Dn, SSZ=(long)Bn*Nn*MP, HSZ=(long)Bn*Nn*Hn;

__device__ __align__(16) float g_x[XSZ], g_xn[XSZ], g_q[XSZ], g_ao[XSZ];
__device__ __align__(16) float g_mem[MSZ], g_k[MSZ], g_v[MSZ], g_vt[MSZ];
__device__ __align__(16) float g_s[SSZ];
__device__ __align__(16) float g_h[HSZ];
__device__ __align__(16) float g_hist[(long)Rn*Bn*Dn];

__global__ void k_save_cls(const float* __restrict__ x, float* __restrict__ dst){
    int i = blockIdx.x*256 + threadIdx.x;
    if (i >= Bn*Dn) return;
    int b = i/Dn, d = i%Dn;
    dst[i] = x[(long)b*Nn*Dn + d];
}
__global__ void k_restore_body(const float* __restrict__ xin, float* __restrict__ x){
    long i = (long)blockIdx.x*256 + threadIdx.x;
    const long per = (long)(Nn-1)*Dn, tot = (long)Bn*per;
    if (i >= tot) return;
    int b = (int)(i/per); long rem = i - (long)b*per;
    long off = (long)b*Nn*Dn + Dn + rem;
    x[off] = xin[off];
}
__global__ void k_build_mem(const float* __restrict__ x, const float* __restrict__ hist,
                            float* __restrict__ mem, int Mr){
    long i = (long)blockIdx.x*256 + threadIdx.x;
    if (i >= MSZ) return;
    int d = (int)(i % Dn); long bt = i / Dn;
    int t = (int)(bt % MP), b = (int)(bt / MP);
    float v = 0.f;
    if (t < Nn)      v = x[((long)b*Nn + t)*Dn + d];
    else if (t < Mr) v = hist[((long)(t-Nn)*Bn + b)*Dn + d];
    mem[i] = v;
}

// batched transpose: v [B][MP][Dn] -> vt [B][Dn][MP]
__global__ void k_transpose(const float* __restrict__ v, float* __restrict__ vt){
    __shared__ float tile[32][33];
    int b = blockIdx.z;
    int t0 = blockIdx.x*32, d0 = blockIdx.y*32;
    const float* src = v + (long)b*MP*Dn;
    float* dst = vt + (long)b*Dn*MP;
    int x = threadIdx.x, y = threadIdx.y;
    #pragma unroll
    for (int i=0;i<32;i+=8){
        int t=t0+y+i, d=d0+x;
        if (t<MP && d<Dn) tile[y+i][x] = src[(long)t*Dn+d];
    }
    __syncthreads();
    #pragma unroll
    for (int i=0;i<32;i+=8){
        int d=d0+y+i, t=t0+x;
        if (d<Dn && t<MP) dst[(long)d*MP+t] = tile[x][y+i];
    }
}

__global__ void k_ln(const float* __restrict__ in, float* __restrict__ out,
                     const float* __restrict__ w, const float* __restrict__ bb){
    long row = blockIdx.x;
    const float* x = in + row*Dn; float* y = out + row*Dn;
    int t = threadIdx.x;
    float v0=x[t], v1=x[t+128], v2=x[t+256];
    __shared__ float sm[4];
    float s = v0+v1+v2;
    #pragma unroll
    for (int o=16;o>0;o>>=1) s += __shfl_xor_sync(0xffffffffu,s,o);
    if ((t&31)==0) sm[t>>5]=s;
    __syncthreads();
    float mu = (sm[0]+sm[1]+sm[2]+sm[3])*(1.f/Dn);
    float c0=v0-mu, c1=v1-mu, c2=v2-mu;
    float q = c0*c0+c1*c1+c2*c2;
    #pragma unroll
    for (int o=16;o>0;o>>=1) q += __shfl_xor_sync(0xffffffffu,q,o);
    __syncthreads();
    if ((t&31)==0) sm[t>>5]=q;
    __syncthreads();
    float rs = rsqrtf((sm[0]+sm[1]+sm[2]+sm[3])*(1.f/Dn) + 1e-6f);
    y[t]     = c0*rs*w[t]     + bb[t];
    y[t+128] = c1*rs*w[t+128] + bb[t+128];
    y[t+256] = c2*rs*w[t+256] + bb[t+256];
}

__global__ void k_softmax(float* __restrict__ sbuf, int Mr){
    long row = blockIdx.x;
    float* p = sbuf + row*MP;
    int t = threadIdx.x;
    float v[3]; float mx = -3.0e38f;
    #pragma unroll
    for (int i=0;i<3;++i){ int idx=t+256*i; v[i] = (idx<Mr)? p[idx] : -3.0e38f; mx = fmaxf(mx,v[i]); }
    __shared__ float sm[8];
    #pragma unroll
    for (int o=16;o>0;o>>=1) mx = fmaxf(mx,__shfl_xor_sync(0xffffffffu,mx,o));
    if ((t&31)==0) sm[t>>5]=mx;
    __syncthreads();
    float m2 = sm[0];
    #pragma unroll
    for (int i=1;i<8;++i) m2 = fmaxf(m2,sm[i]);
    float sum = 0.f;
    #pragma unroll
    for (int i=0;i<3;++i){ int idx=t+256*i; if (idx<Mr){ v[i]=expf(v[i]-m2); sum+=v[i]; } }
    #pragma unroll
    for (int o=16;o>0;o>>=1) sum += __shfl_xor_sync(0xffffffffu,sum,o);
    __syncthreads();
    if ((t&31)==0) sm[t>>5]=sum;
    __syncthreads();
    float tot=0.f;
    #pragma unroll
    for (int i=0;i<8;++i) tot += sm[i];
    float inv = 1.f/tot;
    #pragma unroll
    for (int i=0;i<3;++i){ int idx=t+256*i; if (idx<Mr) p[idx]=v[i]*inv; else if (idx<MP) p[idx]=0.f; }
}

// ---------------------------------------------------------------------------
// BF16 tensor-core GEMM. C = epi( A[M,K] @ B[Nc,K]^T ). K % 32 == 0.
// 128x128 tile, BK=32, 256 thr = 8 warps (4m x 2n), warp tile 32x64,
// mma.m16n8k16.bf16. Smem holds packed bf16x2 words, row stride 20 words
// (16 data + 4 pad; 20 mod 8 == 4 -> conflict-free fragment loads).
// ---------------------------------------------------------------------------
constexpr int BM=128, BN=128, BK=32, LDSW=20;
constexpr int EPI_SCALE=0, EPI_BIAS=1, EPI_LSRES=2, EPI_GELU=3;

__device__ __forceinline__ unsigned pk2(float a, float b){
    __nv_bfloat162 h = __floats2bfloat162_rn(a, b);
    return *(unsigned*)&h;
}
__device__ __forceinline__ void mma16(float* c, const unsigned* a, const unsigned* b){
    asm volatile("mma.sync.aligned.m16n8k16.row.col.f32.bf16.bf16.f32 "
        "{%0,%1,%2,%3}, {%4,%5,%6,%7}, {%8,%9}, {%0,%1,%2,%3};"
        : "+f"(c[0]), "+f"(c[1]), "+f"(c[2]), "+f"(c[3])
        : "r"(a[0]), "r"(a[1]), "r"(a[2]), "r"(a[3]), "r"(b[0]), "r"(b[1]));
}

template<int EPI>
__launch_bounds__(256,2)
__global__ void k_gemm_b(const float* __restrict__ A, int lda,
                         const float* __restrict__ Bm, int ldb,
                         const float* __restrict__ bias, const float* __restrict__ ls,
                         const float* __restrict__ res, float* __restrict__ C, int ldc,
                         int Mrows, int Ncols, int K,
                         long sA, long sB, long sC, float alpha){
    long zb = blockIdx.z;
    A += zb*sA; Bm += zb*sB; C += zb*sC;
    const float* resp = (EPI==EPI_LSRES) ? (res + zb*sC) : nullptr;

    __shared__ unsigned As[BM*LDSW];
    __shared__ unsigned Bs[BN*LDSW];

    int tid = threadIdx.x, lane = tid&31, warp = tid>>5;
    int bm = blockIdx.y*BM, bn = blockIdx.x*BN;
    int wm = (warp>>1)*32, wn = (warp&1)*64;
    int gid = lane>>2, tig = lane&3;

    float acc[2][8][4];
    #pragma unroll
    for (int i=0;i<2;++i)
        #pragma unroll
        for (int j=0;j<8;++j)
            #pragma unroll
            for (int q=0;q<4;++q) acc[i][j][q]=0.f;

    // fill mapping: one row per thread-pair, each half covers 16 k-elements
    int fr = tid>>1;              // 0..127  (row within tile)
    int fk = (tid&1)*16;          // 0 or 16 (k offset within slab)
    int fw = fk>>1;               // word offset 0 or 8

    int nk = K>>5;
    for (int kt=0; kt<nk; ++kt){
        int k0 = kt*BK;
        {   // A tile
            int gm = bm + fr;
            unsigned u[8];
            if (gm < Mrows){
                const float* ap = A + (long)gm*lda + k0 + fk;
                #pragma unroll
                for (int j=0;j<4;++j){
                    float4 v = *(const float4*)(ap + j*4);
                    u[j*2]   = pk2(v.x, v.y);
                    u[j*2+1] = pk2(v.z, v.w);
                }
            } else {
                #pragma unroll
                for (int j=0;j<8;++j) u[j]=0u;
            }
            *(uint4*)&As[fr*LDSW + fw    ] = make_uint4(u[0],u[1],u[2],u[3]);
            *(uint4*)&As[fr*LDSW + fw + 4] = make_uint4(u[4],u[5],u[6],u[7]);
        }
        {   // B tile
            int gn = bn + fr;
            unsigned u[8];
            if (gn < Ncols){
                const float* bp = Bm + (long)gn*ldb + k0 + fk;
                #pragma unroll
                for (int j=0;j<4;++j){
                    float4 v = *(const float4*)(bp + j*4);
                    u[j*2]   = pk2(v.x, v.y);
                    u[j*2+1] = pk2(v.z, v.w);
                }
            } else {
                #pragma unroll
                for (int j=0;j<8;++j) u[j]=0u;
            }
            *(uint4*)&Bs[fr*LDSW + fw    ] = make_uint4(u[0],u[1],u[2],u[3]);
            *(uint4*)&Bs[fr*LDSW + fw + 4] = make_uint4(u[4],u[5],u[6],u[7]);
        }
        __syncthreads();
        #pragma unroll
        for (int ks=0; ks<2; ++ks){
            int kb = ks*8;     // word offset of this k16 step
            unsigned af[2][4], bf[8][2];
            #pragma unroll
            for (int mt=0; mt<2; ++mt){
                int m0 = wm + mt*16;
                af[mt][0] = As[(m0+gid  )*LDSW + kb + tig];
                af[mt][1] = As[(m0+gid+8)*LDSW + kb + tig];
                af[mt][2] = As[(m0+gid  )*LDSW + kb + tig + 4];
                af[mt][3] = As[(m0+gid+8)*LDSW + kb + tig + 4];
            }
            #pragma unroll
            for (int nt=0; nt<8; ++nt){
                int n0 = wn + nt*8;
                bf[nt][0] = Bs[(n0+gid)*LDSW + kb + tig];
                bf[nt][1] = Bs[(n0+gid)*LDSW + kb + tig + 4];
            }
            #pragma unroll
            for (int mt=0; mt<2; ++mt)
                #pragma unroll
                for (int nt=0; nt<8; ++nt)
                    mma16(acc[mt][nt], af[mt], bf[nt]);
        }
        __syncthreads();
    }

    #pragma unroll
    for (int mt=0; mt<2; ++mt){
        int row0 = bm + wm + mt*16 + gid;
        #pragma unroll
        for (int nt=0; nt<8; ++nt){
            int col = bn + wn + nt*8 + 2*tig;
            if (col >= Ncols) continue;   // Ncols even -> covers col+1
            #pragma unroll
            for (int h=0; h<2; ++h){
                int gm = row0 + h*8;
                if (gm >= Mrows) continue;
                long ro = (long)gm*ldc;
                #pragma unroll
                for (int q=0; q<2; ++q){
                    int gn = col + q;
                    float v = acc[mt][nt][h*2+q];
                    if      (EPI==EPI_SCALE) v *= alpha;
                    else if (EPI==EPI_BIAS)  v += bias[gn];
                    else if (EPI==EPI_LSRES) v = (v + bias[gn])*ls[gn] + resp[ro+gn];
                    else { v += bias[gn]; v = 0.5f*v*(1.f + erff(v*0.70710678118654752f)); }
                    C[ro+gn] = v;
                }
            }
        }
    }
}

static inline unsigned cdiv(long a, long b){ return (unsigned)((a+b-1)/b); }

static void gemm(int epi, const float* A, int lda, const float* B, int ldb,
                 const float* bias, const float* ls, const float* res, float* C, int ldc,
                 int M, int Nc, int K, int zb, long sA, long sB, long sC, float alpha){
    dim3 g(cdiv(Nc,BN), cdiv(M,BM), zb), t(256);
    if      (epi==EPI_SCALE) k_gemm_b<EPI_SCALE><<<g,t>>>(A,lda,B,ldb,bias,ls,res,C,ldc,M,Nc,K,sA,sB,sC,alpha);
    else if (epi==EPI_BIAS)  k_gemm_b<EPI_BIAS ><<<g,t>>>(A,lda,B,ldb,bias,ls,res,C,ldc,M,Nc,K,sA,sB,sC,alpha);
    else if (epi==EPI_LSRES) k_gemm_b<EPI_LSRES><<<g,t>>>(A,lda,B,ldb,bias,ls,res,C,ldc,M,Nc,K,sA,sB,sC,alpha);
    else                     k_gemm_b<EPI_GELU ><<<g,t>>>(A,lda,B,ldb,bias,ls,res,C,ldc,M,Nc,K,sA,sB,sC,alpha);
}

extern "C" void kernel_launch(void* const* d_in, const int* in_sizes, int n_in,
                              void* d_out, int out_size){
    const float* in_x     = (const float*)d_in[0];
    const float* norm1_w  = (const float*)d_in[1];
    const float* norm1_b  = (const float*)d_in[2];
    const float* qkv_w    = (const float*)d_in[3];
    const float* qkv_b    = (const float*)d_in[4];
    const float* qn_w     = (const float*)d_in[5];
    const float* qn_b     = (const float*)d_in[6];
    const float* kn_w     = (const float*)d_in[7];
    const float* kn_b     = (const float*)d_in[8];
    const float* an_w     = (const float*)d_in[9];
    const float* an_b     = (const float*)d_in[10];
    const float* proj_w   = (const float*)d_in[11];
    const float* proj_b   = (const float*)d_in[12];
    const float* ls1      = (const float*)d_in[13];
    const float* norm2_w  = (const float*)d_in[14];
    const float* norm2_b  = (const float*)d_in[15];
    const float* fc1_w    = (const float*)d_in[16];
    const float* fc1_b    = (const float*)d_in[17];
    const float* fc2_w    = (const float*)d_in[18];
    const float* fc2_b    = (const float*)d_in[19];
    const float* ls2      = (const float*)d_in[20];

    float *px,*pxn,*pq,*pao,*pmem,*pk,*pv,*pvt,*ps,*ph,*phist;
    cudaGetSymbolAddress((void**)&px,   g_x);
    cudaGetSymbolAddress((void**)&pxn,  g_xn);
    cudaGetSymbolAddress((void**)&pq,   g_q);
    cudaGetSymbolAddress((void**)&pao,  g_ao);
    cudaGetSymbolAddress((void**)&pmem, g_mem);
    cudaGetSymbolAddress((void**)&pk,   g_k);
    cudaGetSymbolAddress((void**)&pv,   g_v);
    cudaGetSymbolAddress((void**)&pvt,  g_vt);
    cudaGetSymbolAddress((void**)&ps,   g_s);
    cudaGetSymbolAddress((void**)&ph,   g_h);
    cudaGetSymbolAddress((void**)&phist,g_hist);

    const float scale = 1.0f / sqrtf((float)Dn);
    const int MX = Bn*Nn;          // 18464
    const int MM = Bn*MP;          // 19456

    cudaMemcpyAsync(px, in_x, XSZ*sizeof(float), cudaMemcpyDeviceToDevice);

    for (int r = 0; r < Rn; ++r){
        int Mr = Nn + r;
        k_save_cls<<<cdiv(Bn*Dn,256),256>>>(px, phist + (long)r*Bn*Dn);
        k_restore_body<<<cdiv((long)Bn*(Nn-1)*Dn,256),256>>>(in_x, px);
        k_build_mem<<<cdiv(MSZ,256),256>>>(px, phist, pmem, Mr);

        for (int l = 0; l < Ln; ++l){
            const float* wq = qkv_w + (long)l*3*Dn*Dn;
            const float* wk = wq + (long)Dn*Dn;
            const float* wv = wk + (long)Dn*Dn;
            const float* bq = qkv_b + (long)l*3*Dn;
            const float* bk = bq + Dn;
            const float* bv = bk + Dn;

            k_ln<<<MX,128>>>(px, pxn, norm1_w + (long)l*Dn, norm1_b + (long)l*Dn);
            gemm(EPI_BIAS, pxn, Dn, wq, Dn, bq, 0, 0, pq, Dn, MX, Dn, Dn, 1,0,0,0, 0.f);
            k_ln<<<MX,128>>>(pq, pq, qn_w + (long)l*Dn, qn_b + (long)l*Dn);

            gemm(EPI_BIAS, pmem, Dn, wk, Dn, bk, 0, 0, pk, Dn, MM, Dn, Dn, 1,0,0,0, 0.f);
            k_ln<<<MM,128>>>(pk, pk, kn_w + (long)l*Dn, kn_b + (long)l*Dn);
            gemm(EPI_BIAS, pmem, Dn, wv, Dn, bv, 0, 0, pv, Dn, MM, Dn, Dn, 1,0,0,0, 0.f);
            k_transpose<<<dim3(cdiv(MP,32),cdiv(Dn,32),Bn), dim3(32,8)>>>(pv, pvt);

            gemm(EPI_SCALE, pq, Dn, pk, Dn, 0,0,0, ps, MP, Nn, MP, Dn,
                 Bn, (long)Nn*Dn, (long)MP*Dn, (long)Nn*MP, scale);
            k_softmax<<<MX,256>>>(ps, Mr);
            gemm(EPI_SCALE, ps, MP, pvt, MP, 0,0,0, pao, Dn, Nn, Dn, MP,
                 Bn, (long)Nn*MP, (long)Dn*MP, (long)Nn*Dn, 1.0f);

            k_ln<<<MX,128>>>(pao, pao, an_w + (long)l*Dn, an_b + (long)l*Dn);
            gemm(EPI_LSRES, pao, Dn, proj_w + (long)l*Dn*Dn, Dn,
                 proj_b + (long)l*Dn, ls1 + (long)l*Dn, px, pxn, Dn, MX, Dn, Dn, 1,0,0,0, 0.f);

            k_ln<<<MX,128>>>(pxn, pq, norm2_w + (long)l*Dn, norm2_b + (long)l*Dn);
            gemm(EPI_GELU, pq, Dn, fc1_w + (long)l*Hn*Dn, Dn,
                 fc1_b + (long)l*Hn, 0, 0, ph, Hn, MX, Hn, Dn, 1,0,0,0, 0.f);
            gemm(EPI_LSRES, ph, Hn, fc2_w + (long)l*Dn*Hn, Hn,
                 fc2_b + (long)l*Dn, ls2 + (long)l*Dn, pxn, px, Dn, MX, Dn, Hn, 1,0,0,0, 0.f);
        }
    }
    cudaMemcpyAsync(d_out, px, XSZ*sizeof(float), cudaMemcpyDeviceToDevice);
}